// round 1
// baseline (speedup 1.0000x reference)
#include <cuda_runtime.h>
#include <cstdint>

// Problem constants
#define B_TOT 2048
#define M_    8
#define N_    10
#define C_    10
#define D_    512
#define K_    64
#define W_    512
#define FIN   138
#define P_    80      // M_*N_
#define BT    64      // batch tile per CTA
#define VC    256     // v-chunk width
#define KT    16      // k-tile depth per stage

// Shared memory layout (in floats)
#define SM_H1   0
#define SM_ZC   (64*512)                 // 32768
#define SM_WS   (SM_ZC + 64*128)         // +8192
#define SM_INT  (SM_WS + 2*KT*VC)        // +8192
#define SMEM_FLOATS (SM_INT + 192)
#define SMEM_BYTES  (SMEM_FLOATS * 4)

__device__ __forceinline__ void cp16(float* dst, const float* src) {
    uint32_t s = (uint32_t)__cvta_generic_to_shared(dst);
    asm volatile("cp.async.cg.shared.global [%0], [%1], 16;" :: "r"(s), "l"(src));
}
__device__ __forceinline__ void cp_commit() { asm volatile("cp.async.commit_group;"); }
__device__ __forceinline__ void cp_wait1()  { asm volatile("cp.async.wait_group 1;"); }

__device__ __forceinline__ unsigned long long pk2(float x, float y) {
    unsigned long long r;
    asm("mov.b64 %0, {%1, %2};" : "=l"(r) : "f"(x), "f"(y));
    return r;
}
__device__ __forceinline__ void fma2(unsigned long long& a, unsigned long long x, unsigned long long y) {
    asm("fma.rn.f32x2 %0, %1, %2, %0;" : "+l"(a) : "l"(x), "l"(y));
}
__device__ __forceinline__ float2 up2(unsigned long long v) {
    float2 r;
    asm("mov.b64 {%0, %1}, %2;" : "=f"(r.x), "=f"(r.y) : "l"(v));
    return r;
}

// One (64 x 256) output chunk of A[64 x ksz] @ B[ksz x 512][:, vc:vc+256].
// A is in shared memory (row stride astride). B streamed from global through a
// double-buffered [16][256] smem tile via cp.async. 8b x 8v register tile per
// thread, packed f32x2 accumulators: acc[b][0..1] cover v = vc+lane*4+{0..3},
// acc[b][2..3] cover v = vc+128+lane*4+{0..3}.
template<int KSZ>
__device__ __forceinline__ void gemm_chunk(
    unsigned long long acc[8][4],
    const float* Asm, int astride,
    const float* __restrict__ gsrc,   // [KSZ][512] row-major
    int vc, float* ws, int warp, int lane, int tid)
{
    constexpr int S = KSZ / KT;

    #pragma unroll
    for (int b = 0; b < 8; b++)
        #pragma unroll
        for (int q = 0; q < 4; q++) acc[b][q] = 0ull;

    // prologue: stage 0
    #pragma unroll
    for (int r = 0; r < 4; r++) {
        int i = tid + r * 256;
        int kk = i >> 6, v4 = i & 63;
        cp16(ws + kk * VC + v4 * 4, gsrc + (size_t)kk * W_ + vc + v4 * 4);
    }
    cp_commit();

    for (int s = 0; s < S; s++) {
        if (s + 1 < S) {
            float* wd = ws + ((s + 1) & 1) * (KT * VC);
            const float* gs = gsrc + (size_t)(s + 1) * KT * W_ + vc;
            #pragma unroll
            for (int r = 0; r < 4; r++) {
                int i = tid + r * 256;
                int kk = i >> 6, v4 = i & 63;
                cp16(wd + kk * VC + v4 * 4, gs + (size_t)kk * W_ + v4 * 4);
            }
        }
        cp_commit();            // (possibly empty) group keeps wait-count consistent
        cp_wait1();             // stage s resident
        __syncthreads();

        const float* wb = ws + (s & 1) * (KT * VC);
        const int kbase = s * KT;

        #pragma unroll
        for (int kk = 0; kk < KT; kk += 4) {
            float4 av[8];
            #pragma unroll
            for (int b = 0; b < 8; b++)
                av[b] = *reinterpret_cast<const float4*>(
                    Asm + (size_t)(warp * 8 + b) * astride + kbase + kk);
            #pragma unroll
            for (int kq = 0; kq < 4; kq++) {
                ulonglong2 bv0 = *reinterpret_cast<const ulonglong2*>(wb + (kk + kq) * VC + lane * 4);
                ulonglong2 bv1 = *reinterpret_cast<const ulonglong2*>(wb + (kk + kq) * VC + 128 + lane * 4);
                #pragma unroll
                for (int b = 0; b < 8; b++) {
                    float a = (kq == 0) ? av[b].x : (kq == 1) ? av[b].y : (kq == 2) ? av[b].z : av[b].w;
                    unsigned long long ap = pk2(a, a);
                    fma2(acc[b][0], ap, bv0.x);
                    fma2(acc[b][1], ap, bv0.y);
                    fma2(acc[b][2], ap, bv1.x);
                    fma2(acc[b][3], ap, bv1.y);
                }
            }
        }
        __syncthreads();        // buffer safe to overwrite next iteration
    }
}

extern "C" __global__ void __launch_bounds__(256, 1)
mc_kernel(const int* __restrict__ y, const float* __restrict__ zL, const float* __restrict__ zR,
          const int* __restrict__ idxL, const int* __restrict__ idxR,
          const float* __restrict__ W1, const float* __restrict__ b1,
          const float* __restrict__ W2, const float* __restrict__ b2,
          const float* __restrict__ W3, const float* __restrict__ b3,
          float* __restrict__ out)
{
    extern __shared__ float sm[];
    float* h1 = sm + SM_H1;          // [64][512]
    float* zc = sm + SM_ZC;          // [64][128]
    float* ws = sm + SM_WS;          // [2][16][256]
    int*   ints = (int*)(sm + SM_INT);
    int*   ys   = ints;              // [64]
    int*   idxs = ints + 64;         // [128]

    const int p  = blockIdx.x;                 // pair index m*N + n
    const int m  = p / N_;
    const int n  = p - m * N_;
    const int b0 = blockIdx.y * BT;
    const int tid  = threadIdx.x;
    const int lane = tid & 31;
    const int warp = tid >> 5;

    if (tid < 64)      ys[tid] = y[(size_t)(b0 + tid) * N_ + n];
    else if (tid < 192) {
        int j = tid - 64;
        idxs[j] = (j < 64) ? idxL[m * K_ + j] : idxR[m * K_ + (j - 64)];
    }
    __syncthreads();

    // zcat tile: zc[b][j] = (j<64 ? zL : zR)[b0+b][idx[j]]
    for (int i = tid; i < BT * 128; i += 256) {
        int b = i >> 7, j = i & 127;
        zc[i] = (j < 64) ? zL[(size_t)(b0 + b) * D_ + idxs[j]]
                         : zR[(size_t)(b0 + b) * D_ + idxs[j]];
    }
    // visibility guaranteed by __syncthreads inside gemm_chunk before first compute

    const float* W1p = W1 + (size_t)p * FIN * W_;
    const float* G1  = W1p + (size_t)C_ * W_;          // rows C..C+127: [zL|zR] weights
    const float* b1p = b1 + (size_t)p * W_;
    const float* W2p = W2 + (size_t)p * W_ * W_;
    const float* b2p = b2 + (size_t)p * W_;
    const float* W3p = W3 + (size_t)p * W_;

    unsigned long long acc[8][4];

    // ---------- Phase 1: h1 = relu(zc @ G1 + W1[y] + b1) ----------
    #pragma unroll 1
    for (int vc = 0; vc < W_; vc += VC) {
        gemm_chunk<128>(acc, zc, 128, G1, vc, ws, warp, lane, tid);
        #pragma unroll
        for (int b = 0; b < 8; b++) {
            int row = warp * 8 + b;
            const float* wy = W1p + (size_t)ys[row] * W_;   // one-hot row gather
            #pragma unroll
            for (int g = 0; g < 2; g++) {
                int base = vc + g * 128 + lane * 4;
                float4 ad = *reinterpret_cast<const float4*>(wy + base);
                float4 bb = *reinterpret_cast<const float4*>(b1p + base);
                float2 x0 = up2(acc[b][g * 2 + 0]);
                float2 x1 = up2(acc[b][g * 2 + 1]);
                float4 r;
                r.x = fmaxf(x0.x + ad.x + bb.x, 0.f);
                r.y = fmaxf(x0.y + ad.y + bb.y, 0.f);
                r.z = fmaxf(x1.x + ad.z + bb.z, 0.f);
                r.w = fmaxf(x1.y + ad.w + bb.w, 0.f);
                *reinterpret_cast<float4*>(h1 + (size_t)row * W_ + base) = r;
            }
        }
    }

    // ---------- Phase 2: out = relu(h1 @ W2 + b2) . W3 + b3 (h2 never stored) ----------
    float po[8];
    #pragma unroll
    for (int b = 0; b < 8; b++) po[b] = 0.f;

    #pragma unroll 1
    for (int vc = 0; vc < W_; vc += VC) {
        gemm_chunk<512>(acc, h1, 512, W2p, vc, ws, warp, lane, tid);
        #pragma unroll
        for (int b = 0; b < 8; b++) {
            #pragma unroll
            for (int g = 0; g < 2; g++) {
                int base = vc + g * 128 + lane * 4;
                float4 bb = *reinterpret_cast<const float4*>(b2p + base);
                float4 w3 = *reinterpret_cast<const float4*>(W3p + base);
                float2 x0 = up2(acc[b][g * 2 + 0]);
                float2 x1 = up2(acc[b][g * 2 + 1]);
                po[b] += fmaxf(x0.x + bb.x, 0.f) * w3.x
                       + fmaxf(x0.y + bb.y, 0.f) * w3.y
                       + fmaxf(x1.x + bb.z, 0.f) * w3.z
                       + fmaxf(x1.y + bb.w, 0.f) * w3.w;
            }
        }
    }

    // lanes of a warp share the same 8 batch rows -> butterfly reduce over v
    #pragma unroll
    for (int b = 0; b < 8; b++) {
        #pragma unroll
        for (int off = 16; off; off >>= 1)
            po[b] += __shfl_xor_sync(0xffffffffu, po[b], off);
    }
    if (lane == 0) {
        float bias3 = b3[p];
        #pragma unroll
        for (int b = 0; b < 8; b++)
            out[(size_t)(b0 + warp * 8 + b) * P_ + p] = po[b] + bias3;
    }
}

extern "C" void kernel_launch(void* const* d_in, const int* in_sizes, int n_in,
                              void* d_out, int out_size)
{
    (void)in_sizes; (void)n_in; (void)out_size;
    const int*   y    = (const int*)  d_in[0];
    const float* zL   = (const float*)d_in[1];
    const float* zR   = (const float*)d_in[2];
    const int*   idxL = (const int*)  d_in[3];
    const int*   idxR = (const int*)  d_in[4];
    const float* W1   = (const float*)d_in[5];
    const float* b1   = (const float*)d_in[6];
    const float* W2   = (const float*)d_in[7];
    const float* b2   = (const float*)d_in[8];
    const float* W3   = (const float*)d_in[9];
    const float* b3   = (const float*)d_in[10];
    float* out = (float*)d_out;

    cudaFuncSetAttribute(mc_kernel, cudaFuncAttributeMaxDynamicSharedMemorySize, SMEM_BYTES);
    dim3 grid(P_, B_TOT / BT);
    mc_kernel<<<grid, 256, SMEM_BYTES>>>(y, zL, zR, idxL, idxR, W1, b1, W2, b2, W3, b3, out);
}